// round 11
// baseline (speedup 1.0000x reference)
#include <cuda_runtime.h>
#include <math.h>

#define BATCH   64
#define HID     512
#define EMBD    200
#define VOCAB   32000
#define SRCLEN  64
#define TGTLEN  64
#define SB      (BATCH*HID)
#define FCBLK   500   /* 32000 / 64 */

typedef unsigned long long ull;

__device__ __forceinline__ ull pack2(float a, float b) {
    ull r; asm("mov.b64 %0, {%1,%2};" : "=l"(r) : "f"(a), "f"(b)); return r;
}
__device__ __forceinline__ ull ffma2(ull a, ull b, ull c) {
    ull d; asm("fma.rn.f32x2 %0, %1, %2, %3;" : "=l"(d) : "l"(a), "l"(b), "l"(c)); return d;
}
__device__ __forceinline__ float2 unpk(ull v) {
    float2 r; asm("mov.b64 {%0,%1}, %2;" : "=f"(r.x), "=f"(r.y) : "l"(v)); return r;
}

// ---- static scratch ----
__device__ __align__(16) float g_gp0[12*32*64*64];
__device__ __align__(16) float g_gp1[16*32*64*64];
__device__ __align__(16) float g_h0f[2*SB], g_c0f[2*SB];
__device__ __align__(16) float g_h1f[2*SB], g_c1f[2*SB];
__device__ int   g_xtok[BATCH];
__device__ __align__(16) float g_pval[FCBLK*BATCH];
__device__ int   g_pidx[FCBLK*BATCH];
__device__ int   g_cnt0[32], g_cnt1[32], g_cntFC;

__global__ void init_kernel(const int* __restrict__ target) {
    int i = blockIdx.x*blockDim.x + threadIdx.x;
    int stride = gridDim.x*blockDim.x;
    for (int k = i; k < 2*SB; k += stride) {
        g_h0f[k]=0.f; g_c0f[k]=0.f; g_h1f[k]=0.f; g_c1f[k]=0.f;
    }
    if (i < BATCH) g_xtok[i] = target[i];
    if (i < 32) { g_cnt0[i]=0; g_cnt1[i]=0; }
    if (i == 32) g_cntFC = 0;
}

__device__ __forceinline__ void lstm4(float4 i4, float4 f4, float4 g4, float4 o4,
                                      float4 c4, float4& cn, float4& hn) {
    float iv, fv, gv, ov, cc;
    iv=1.f/(1.f+expf(-i4.x)); fv=1.f/(1.f+expf(-f4.x)); gv=tanhf(g4.x); ov=1.f/(1.f+expf(-o4.x));
    cc=fv*c4.x+iv*gv; cn.x=cc; hn.x=ov*tanhf(cc);
    iv=1.f/(1.f+expf(-i4.y)); fv=1.f/(1.f+expf(-f4.y)); gv=tanhf(g4.y); ov=1.f/(1.f+expf(-o4.y));
    cc=fv*c4.y+iv*gv; cn.y=cc; hn.y=ov*tanhf(cc);
    iv=1.f/(1.f+expf(-i4.z)); fv=1.f/(1.f+expf(-f4.z)); gv=tanhf(g4.z); ov=1.f/(1.f+expf(-o4.z));
    cc=fv*c4.z+iv*gv; cn.z=cc; hn.z=ov*tanhf(cc);
    iv=1.f/(1.f+expf(-i4.w)); fv=1.f/(1.f+expf(-f4.w)); gv=tanhf(g4.w); ov=1.f/(1.f+expf(-o4.w));
    cc=fv*c4.w+iv*gv; cn.w=cc; hn.w=ov*tanhf(cc);
}

// ============================================================================
// Fused LSTM layer-step GEMM + epilogue.
// Tile ti covers hidden units ti*16..+15 as 64 gate-interleaved columns.
// mode 0: layer0 only (grid 32x12); mode 1: layer1 only (grid 32x16);
// mode 2: pair = layer1(step s, p1) [y<16] + layer0(step s+1, p0) [y>=16].
// Last block per tile sums partials in fixed y order, applies activations,
// writes h/c at parity p (inputs read at parity p^1).
// ============================================================================
__global__ void __launch_bounds__(128) gates_fused(
    const float* __restrict__ Wih0, const float* __restrict__ Whh0,
    const float* __restrict__ bih0_, const float* __restrict__ bhh0_,
    const float* __restrict__ Wih1, const float* __restrict__ Whh1,
    const float* __restrict__ bih1_, const float* __restrict__ bhh1_,
    const float* __restrict__ emb, const int* __restrict__ toks,
    int use_xtok, int mode, int p0, int p1)
{
    __shared__ __align__(16) float Ws[2][8][72];
    __shared__ __align__(16) float Xs[2][8][72];
    __shared__ int stoks[64];
    __shared__ int s_last;

    int tid = threadIdx.x, ti = blockIdx.x, y = blockIdx.y;
    int layer = (mode == 2) ? (y < 16 ? 1 : 0) : mode;
    if (mode == 2 && layer == 0) y -= 16;
    int p = layer ? p1 : p0;

    const float *Wih, *Whh, *bih, *bhh, *Xih;
    int Kih, nih, nsplit, ldXih, IHS;
    float *parts; int *cnt;
    const float *hprev, *cprev; float *hout, *cout;
    if (layer == 0) {
        Wih=Wih0; Whh=Whh0; bih=bih0_; bhh=bhh0_;
        Kih=EMBD; nih=4; IHS=56; nsplit=12;
        Xih=emb; ldXih=EMBD;
        parts=g_gp0; cnt=g_cnt0;
        hprev=g_h0f+(p^1)*SB; cprev=g_c0f+(p^1)*SB;
        hout =g_h0f+p*SB;     cout =g_c0f+p*SB;
    } else {
        Wih=Wih1; Whh=Whh1; bih=bih1_; bhh=bhh1_;
        Kih=HID; nih=8; IHS=64; nsplit=16;
        Xih=g_h0f+p1*SB; ldXih=HID;
        parts=g_gp1; cnt=g_cnt1;
        hprev=g_h1f+(p^1)*SB; cprev=g_c1f+(p^1)*SB;
        hout =g_h1f+p*SB;     cout =g_c1f+p*SB;
    }

    const float *W, *X; int ldW, ldX, kbeg, kend;
    int isih = (y < nih);
    if (isih) {
        W=Wih; ldW=Kih; kbeg=y*IHS; kend=kbeg+IHS; if (kend>Kih) kend=Kih;
        X=Xih; ldX=ldXih;
    } else {
        W=Whh; ldW=HID; kbeg=(y-nih)*64; kend=kbeg+64;
        X=hprev; ldX=HID;
    }
    int gath = (layer == 0) && isih;
    if (tid < 64)
        stoks[tid] = gath ? (use_xtok ? g_xtok[tid] : toks[tid]) : tid;
    __syncthreads();

    int l = tid & 31, w = tid >> 5;
    int rg = (w & 1)*8 + (l & 7);     // batch rows rg*4..+3
    int cg = (w >> 1)*4 + (l >> 3);   // cols cg*8..+7
    int wj = tid >> 1, wk = (tid & 1)*4;
    int jr = (wj >> 4)*512 + ti*16 + (wj & 15);  // gate-interleaved W row

    ull acc[4][4];
    #pragma unroll
    for (int r = 0; r < 4; ++r)
        #pragma unroll
        for (int u = 0; u < 4; ++u) acc[r][u] = 0ULL;

    const float* Wp = W + (size_t)jr*ldW + wk;
    const float* Xp = X + (size_t)stoks[wj]*ldX + wk;
    int nch = (kend - kbeg) >> 3;

    float4 wv = *(const float4*)&Wp[kbeg];
    float4 xv = *(const float4*)&Xp[kbeg];
    Ws[0][wk+0][wj]=wv.x; Ws[0][wk+1][wj]=wv.y; Ws[0][wk+2][wj]=wv.z; Ws[0][wk+3][wj]=wv.w;
    Xs[0][wk+0][wj]=xv.x; Xs[0][wk+1][wj]=xv.y; Xs[0][wk+2][wj]=xv.z; Xs[0][wk+3][wj]=xv.w;
    __syncthreads();
    if (nch > 1) {
        wv = *(const float4*)&Wp[kbeg+8];
        xv = *(const float4*)&Xp[kbeg+8];
    }

    for (int c = 0; c < nch; ++c) {
        int cb = c & 1;
        if (c + 1 < nch) {
            int nb = cb ^ 1;
            Ws[nb][wk+0][wj]=wv.x; Ws[nb][wk+1][wj]=wv.y;
            Ws[nb][wk+2][wj]=wv.z; Ws[nb][wk+3][wj]=wv.w;
            Xs[nb][wk+0][wj]=xv.x; Xs[nb][wk+1][wj]=xv.y;
            Xs[nb][wk+2][wj]=xv.z; Xs[nb][wk+3][wj]=xv.w;
        }
        if (c + 2 < nch) {
            int k0 = kbeg + (c+2)*8;
            wv = *(const float4*)&Wp[k0];
            xv = *(const float4*)&Xp[k0];
        }
        #pragma unroll
        for (int q = 0; q < 8; ++q) {
            float4 x4 = *(const float4*)&Xs[cb][q][rg*4];
            ull w0 = *(const ull*)&Ws[cb][q][cg*8];
            ull w1 = *(const ull*)&Ws[cb][q][cg*8+2];
            ull w2 = *(const ull*)&Ws[cb][q][cg*8+4];
            ull w3 = *(const ull*)&Ws[cb][q][cg*8+6];
            ull xr;
            xr = pack2(x4.x, x4.x);
            acc[0][0]=ffma2(xr,w0,acc[0][0]); acc[0][1]=ffma2(xr,w1,acc[0][1]);
            acc[0][2]=ffma2(xr,w2,acc[0][2]); acc[0][3]=ffma2(xr,w3,acc[0][3]);
            xr = pack2(x4.y, x4.y);
            acc[1][0]=ffma2(xr,w0,acc[1][0]); acc[1][1]=ffma2(xr,w1,acc[1][1]);
            acc[1][2]=ffma2(xr,w2,acc[1][2]); acc[1][3]=ffma2(xr,w3,acc[1][3]);
            xr = pack2(x4.z, x4.z);
            acc[2][0]=ffma2(xr,w0,acc[2][0]); acc[2][1]=ffma2(xr,w1,acc[2][1]);
            acc[2][2]=ffma2(xr,w2,acc[2][2]); acc[2][3]=ffma2(xr,w3,acc[2][3]);
            xr = pack2(x4.w, x4.w);
            acc[3][0]=ffma2(xr,w0,acc[3][0]); acc[3][1]=ffma2(xr,w1,acc[3][1]);
            acc[3][2]=ffma2(xr,w2,acc[3][2]); acc[3][3]=ffma2(xr,w3,acc[3][3]);
        }
        __syncthreads();
    }

    // store partials: parts[y][ti][b][64]
    #pragma unroll
    for (int r = 0; r < 4; ++r) {
        int b = rg*4 + r;
        float2 q0 = unpk(acc[r][0]), q1 = unpk(acc[r][1]);
        float2 q2 = unpk(acc[r][2]), q3 = unpk(acc[r][3]);
        float* dst = parts + (((size_t)y*32 + ti)*64 + b)*64 + cg*8;
        *(float4*)dst       = make_float4(q0.x, q0.y, q1.x, q1.y);
        *(float4*)(dst + 4) = make_float4(q2.x, q2.y, q3.x, q3.y);
    }

    __threadfence();
    __syncthreads();
    if (tid == 0) {
        int old = atomicAdd(&cnt[ti], 1);
        s_last = (old == nsplit - 1);
    }
    __syncthreads();

    if (s_last) {
        int b = tid >> 1, uh = (tid & 1)*8, hj0 = ti*16;
        float4 sA[4], sB[4];
        #pragma unroll
        for (int g = 0; g < 4; ++g) {
            const float* b1 = bih + g*512 + hj0 + uh;
            const float* b2 = bhh + g*512 + hj0 + uh;
            float4 x1 = *(const float4*)b1, x2 = *(const float4*)b2;
            sA[g] = make_float4(x1.x+x2.x, x1.y+x2.y, x1.z+x2.z, x1.w+x2.w);
            float4 y1 = *(const float4*)(b1+4), y2 = *(const float4*)(b2+4);
            sB[g] = make_float4(y1.x+y2.x, y1.y+y2.y, y1.z+y2.z, y1.w+y2.w);
        }
        for (int y2 = 0; y2 < nsplit; ++y2) {
            const float* base = parts + (((size_t)y2*32 + ti)*64 + b)*64;
            #pragma unroll
            for (int g = 0; g < 4; ++g) {
                float4 v1 = __ldcg((const float4*)(base + g*16 + uh));
                float4 v2 = __ldcg((const float4*)(base + g*16 + uh + 4));
                sA[g].x+=v1.x; sA[g].y+=v1.y; sA[g].z+=v1.z; sA[g].w+=v1.w;
                sB[g].x+=v2.x; sB[g].y+=v2.y; sB[g].z+=v2.z; sB[g].w+=v2.w;
            }
        }
        int idx = b*HID + hj0 + uh;
        float4 c1 = *(const float4*)&cprev[idx];
        float4 c2 = *(const float4*)&cprev[idx+4];
        float4 cn1, hn1, cn2, hn2;
        lstm4(sA[0], sA[1], sA[2], sA[3], c1, cn1, hn1);
        lstm4(sB[0], sB[1], sB[2], sB[3], c2, cn2, hn2);
        *(float4*)&cout[idx]   = cn1;  *(float4*)&cout[idx+4] = cn2;
        *(float4*)&hout[idx]   = hn1;  *(float4*)&hout[idx+4] = hn2;
        if (tid == 0) cnt[ti] = 0;
    }
}

// ============================================================================
// FC + argmax + token select, fully fused. 500 blocks x 256 thr,
// tile 64 vocab x 64 batch, K=512 pipelined. Last block (atomic counter)
// does the deterministic global argmax (ascending, lowest-index ties).
// ============================================================================
__global__ void __launch_bounds__(256) fc_fused(
    const float* __restrict__ fcW, const float* __restrict__ fcb,
    float* __restrict__ out,
    const int* __restrict__ target, const int* __restrict__ tfmask,
    int t, int p1)
{
    __shared__ __align__(16) float Ws[2][16][72];
    __shared__ __align__(16) float Hs[2][16][72];
    __shared__ float rval[BATCH*16];
    __shared__ int   ridx[BATCH*16];
    __shared__ float sv[256];
    __shared__ int   si[256];
    __shared__ int   s_last;

    int tid = threadIdx.x, v0 = blockIdx.x*64;
    int l = tid & 31, w = tid >> 5;
    int rg = (w & 1)*8 + (l & 7);     // batch rows rg*4..+3
    int cg = (w >> 1)*4 + (l >> 3);   // cols cg*4..+3
    int wj = tid >> 2, wk = (tid & 3)*4;

    ull acc[4][2];
    #pragma unroll
    for (int r = 0; r < 4; ++r) { acc[r][0]=0ULL; acc[r][1]=0ULL; }

    const float* h1p = g_h1f + (size_t)p1*SB;
    const float* Wp = fcW + (size_t)(v0 + wj)*HID + wk;
    const float* Hp = h1p + (size_t)wj*HID + wk;

    const int NCH = HID / 16;   // 32

    float4 wa = *(const float4*)&Wp[0];
    float4 ha = *(const float4*)&Hp[0];
    Ws[0][wk+0][wj]=wa.x; Ws[0][wk+1][wj]=wa.y; Ws[0][wk+2][wj]=wa.z; Ws[0][wk+3][wj]=wa.w;
    Hs[0][wk+0][wj]=ha.x; Hs[0][wk+1][wj]=ha.y; Hs[0][wk+2][wj]=ha.z; Hs[0][wk+3][wj]=ha.w;
    __syncthreads();
    wa = *(const float4*)&Wp[16];
    ha = *(const float4*)&Hp[16];

    for (int c = 0; c < NCH; ++c) {
        int cb = c & 1;
        if (c + 1 < NCH) {
            int nb = cb ^ 1;
            Ws[nb][wk+0][wj]=wa.x; Ws[nb][wk+1][wj]=wa.y;
            Ws[nb][wk+2][wj]=wa.z; Ws[nb][wk+3][wj]=wa.w;
            Hs[nb][wk+0][wj]=ha.x; Hs[nb][wk+1][wj]=ha.y;
            Hs[nb][wk+2][wj]=ha.z; Hs[nb][wk+3][wj]=ha.w;
        }
        if (c + 2 < NCH) {
            int k0 = (c+2)*16;
            wa = *(const float4*)&Wp[k0];
            ha = *(const float4*)&Hp[k0];
        }
        #pragma unroll
        for (int q = 0; q < 16; ++q) {
            float4 x4 = *(const float4*)&Hs[cb][q][rg*4];
            ull w0 = *(const ull*)&Ws[cb][q][cg*4];
            ull w1 = *(const ull*)&Ws[cb][q][cg*4+2];
            ull xr;
            xr = pack2(x4.x, x4.x);
            acc[0][0]=ffma2(xr,w0,acc[0][0]); acc[0][1]=ffma2(xr,w1,acc[0][1]);
            xr = pack2(x4.y, x4.y);
            acc[1][0]=ffma2(xr,w0,acc[1][0]); acc[1][1]=ffma2(xr,w1,acc[1][1]);
            xr = pack2(x4.z, x4.z);
            acc[2][0]=ffma2(xr,w0,acc[2][0]); acc[2][1]=ffma2(xr,w1,acc[2][1]);
            xr = pack2(x4.w, x4.w);
            acc[3][0]=ffma2(xr,w0,acc[3][0]); acc[3][1]=ffma2(xr,w1,acc[3][1]);
        }
        __syncthreads();
    }

    float4 bv = *(const float4*)&fcb[v0 + cg*4];

    #pragma unroll
    for (int r = 0; r < 4; ++r) {
        int b = rg*4 + r;
        float2 t0 = unpk(acc[r][0]), t1 = unpk(acc[r][1]);
        float v_0 = t0.x + bv.x, v_1 = t0.y + bv.y;
        float v_2 = t1.x + bv.z, v_3 = t1.y + bv.w;
        *(float4*)(out + (size_t)b*VOCAB + v0 + cg*4) = make_float4(v_0, v_1, v_2, v_3);
        float best = v_0; int bi = 0;
        if (v_1 > best) { best = v_1; bi = 1; }
        if (v_2 > best) { best = v_2; bi = 2; }
        if (v_3 > best) { best = v_3; bi = 3; }
        rval[b*16 + cg] = best;
        ridx[b*16 + cg] = v0 + cg*4 + bi;
    }
    __syncthreads();
    if (tid < BATCH) {
        float best = rval[tid*16]; int bi = ridx[tid*16];
        #pragma unroll
        for (int u = 1; u < 16; ++u) {
            float v = rval[tid*16 + u];
            if (v > best) { best = v; bi = ridx[tid*16 + u]; }
        }
        g_pval[blockIdx.x*BATCH + tid] = best;
        g_pidx[blockIdx.x*BATCH + tid] = bi;
    }

    __threadfence();
    __syncthreads();
    if (tid == 0) {
        int old = atomicAdd(&g_cntFC, 1);
        s_last = (old == (int)gridDim.x - 1);
    }
    __syncthreads();

    if (s_last) {
        int b = tid >> 2, seg = tid & 3;
        const int per = FCBLK / 4;  // 125
        int q0 = seg*per;
        float best = -3.4e38f; int bi = 0;
        for (int q = q0; q < q0 + per; ++q) {
            float v = __ldcg(&g_pval[q*BATCH + b]);
            if (v > best) { best = v; bi = __ldcg(&g_pidx[q*BATCH + b]); }
        }
        sv[tid] = best; si[tid] = bi;
        __syncthreads();
        if (seg == 0) {
            #pragma unroll
            for (int u = 1; u < 4; ++u) {
                float v = sv[tid + u];
                if (v > best) { best = v; bi = si[tid + u]; }
            }
            g_xtok[b] = (tfmask[t] > 0) ? target[t*BATCH + b] : bi;
        }
        if (tid == 0) g_cntFC = 0;
    }
}

extern "C" void kernel_launch(void* const* d_in, const int* in_sizes, int n_in,
                              void* d_out, int out_size)
{
    const float *enc_embed,*dec_embed,*fcW,*fcb;
    const float *eWih0,*eWhh0,*ebih0,*ebhh0,*eWih1,*eWhh1,*ebih1,*ebhh1;
    const float *dWih0,*dWhh0,*dbih0,*dbhh0,*dWih1,*dWhh1,*dbih1,*dbhh1;
    const int *src,*target,*tfmask;

    if (in_sizes[0] == SRCLEN*BATCH) {
        src=(const int*)d_in[0]; target=(const int*)d_in[1]; tfmask=(const int*)d_in[2];
        enc_embed=(const float*)d_in[3]; dec_embed=(const float*)d_in[4];
        eWih0=(const float*)d_in[5];  eWhh0=(const float*)d_in[6];
        ebih0=(const float*)d_in[7];  ebhh0=(const float*)d_in[8];
        eWih1=(const float*)d_in[9];  eWhh1=(const float*)d_in[10];
        ebih1=(const float*)d_in[11]; ebhh1=(const float*)d_in[12];
        dWih0=(const float*)d_in[13]; dWhh0=(const float*)d_in[14];
        dbih0=(const float*)d_in[15]; dbhh0=(const float*)d_in[16];
        dWih1=(const float*)d_in[17]; dWhh1=(const float*)d_in[18];
        dbih1=(const float*)d_in[19]; dbhh1=(const float*)d_in[20];
        fcW=(const float*)d_in[21];   fcb=(const float*)d_in[22];
    } else {
        enc_embed=(const float*)d_in[0];
        eWih0=(const float*)d_in[1];  eWhh0=(const float*)d_in[2];
        ebih0=(const float*)d_in[3];  ebhh0=(const float*)d_in[4];
        eWih1=(const float*)d_in[5];  eWhh1=(const float*)d_in[6];
        ebih1=(const float*)d_in[7];  ebhh1=(const float*)d_in[8];
        dec_embed=(const float*)d_in[9];
        dWih0=(const float*)d_in[10]; dWhh0=(const float*)d_in[11];
        dbih0=(const float*)d_in[12]; dbhh0=(const float*)d_in[13];
        dWih1=(const float*)d_in[14]; dWhh1=(const float*)d_in[15];
        dbih1=(const float*)d_in[16]; dbhh1=(const float*)d_in[17];
        fcW=(const float*)d_in[18];   fcb=(const float*)d_in[19];
        src=(const int*)d_in[20]; target=(const int*)d_in[21]; tfmask=(const int*)d_in[22];
    }

    float* out = (float*)d_out;
    cudaMemsetAsync(out, 0, (size_t)BATCH * VOCAB * sizeof(float));
    init_kernel<<<64, 256>>>(target);

    // ---- encoder, software-pipelined across layers ----
    // L0(0)
    gates_fused<<<dim3(32,12),128>>>(eWih0,eWhh0,ebih0,ebhh0, eWih1,eWhh1,ebih1,ebhh1,
                                     enc_embed, src, 0, /*mode*/0, /*p0*/0, /*p1*/0);
    // pair(s) = L1(s) + L0(s+1), s = 0..62
    for (int s = 0; s < SRCLEN-1; ++s) {
        gates_fused<<<dim3(32,28),128>>>(eWih0,eWhh0,ebih0,ebhh0, eWih1,eWhh1,ebih1,ebhh1,
                                         enc_embed, src + (s+1)*BATCH, 0,
                                         /*mode*/2, /*p0*/(s+1)&1, /*p1*/s&1);
    }
    // L1(63)
    gates_fused<<<dim3(32,16),128>>>(eWih0,eWhh0,ebih0,ebhh0, eWih1,eWhh1,ebih1,ebhh1,
                                     enc_embed, src, 0, /*mode*/1, /*p0*/0, /*p1*/(SRCLEN-1)&1);

    // ---- decoder ----
    for (int t = 1; t < TGTLEN; ++t) {
        int p = (SRCLEN - 1 + t) & 1;
        gates_fused<<<dim3(32,12),128>>>(dWih0,dWhh0,dbih0,dbhh0, dWih1,dWhh1,dbih1,dbhh1,
                                         dec_embed, src, /*use_xtok*/1, /*mode*/0, p, p);
        gates_fused<<<dim3(32,16),128>>>(dWih0,dWhh0,dbih0,dbhh0, dWih1,dWhh1,dbih1,dbhh1,
                                         dec_embed, src, 0, /*mode*/1, p, p);
        fc_fused<<<FCBLK,256>>>(fcW, fcb, out + (size_t)t*BATCH*VOCAB,
                                target, tfmask, t, p);
    }
}

// round 12
// speedup vs baseline: 1.0123x; 1.0123x over previous
#include <cuda_runtime.h>
#include <math.h>

#define BATCH   64
#define HID     512
#define EMBD    200
#define VOCAB   32000
#define SRCLEN  64
#define TGTLEN  64
#define SB      (BATCH*HID)
#define FCBLK   500   /* 32000 / 64 */

typedef unsigned long long ull;

__device__ __forceinline__ ull pack2(float a, float b) {
    ull r; asm("mov.b64 %0, {%1,%2};" : "=l"(r) : "f"(a), "f"(b)); return r;
}
__device__ __forceinline__ ull ffma2(ull a, ull b, ull c) {
    ull d; asm("fma.rn.f32x2 %0, %1, %2, %3;" : "=l"(d) : "l"(a), "l"(b), "l"(c)); return d;
}
__device__ __forceinline__ float2 unpk(ull v) {
    float2 r; asm("mov.b64 {%0,%1}, %2;" : "=f"(r.x), "=f"(r.y) : "l"(v)); return r;
}

// ---- static scratch ----
__device__ __align__(16) float g_gp0[12*32*64*64];
__device__ __align__(16) float g_gp1[16*32*64*64];
__device__ __align__(16) float g_h0f[2*SB], g_c0f[2*SB];
__device__ __align__(16) float g_h1f[2*SB], g_c1f[2*SB];
__device__ int   g_xtok[BATCH];
__device__ __align__(16) float g_pval[FCBLK*BATCH];
__device__ int   g_pidx[FCBLK*BATCH];
__device__ int   g_cnt0[32], g_cnt1[32], g_cntFC;

__global__ void init_kernel(const int* __restrict__ target) {
    int i = blockIdx.x*blockDim.x + threadIdx.x;
    int stride = gridDim.x*blockDim.x;
    for (int k = i; k < 2*SB; k += stride) {
        g_h0f[k]=0.f; g_c0f[k]=0.f; g_h1f[k]=0.f; g_c1f[k]=0.f;
    }
    if (i < BATCH) g_xtok[i] = target[i];
    if (i < 32) { g_cnt0[i]=0; g_cnt1[i]=0; }
    if (i == 32) g_cntFC = 0;
}

__device__ __forceinline__ void lstm4(float4 i4, float4 f4, float4 g4, float4 o4,
                                      float4 c4, float4& cn, float4& hn) {
    float iv, fv, gv, ov, cc;
    iv=1.f/(1.f+expf(-i4.x)); fv=1.f/(1.f+expf(-f4.x)); gv=tanhf(g4.x); ov=1.f/(1.f+expf(-o4.x));
    cc=fv*c4.x+iv*gv; cn.x=cc; hn.x=ov*tanhf(cc);
    iv=1.f/(1.f+expf(-i4.y)); fv=1.f/(1.f+expf(-f4.y)); gv=tanhf(g4.y); ov=1.f/(1.f+expf(-o4.y));
    cc=fv*c4.y+iv*gv; cn.y=cc; hn.y=ov*tanhf(cc);
    iv=1.f/(1.f+expf(-i4.z)); fv=1.f/(1.f+expf(-f4.z)); gv=tanhf(g4.z); ov=1.f/(1.f+expf(-o4.z));
    cc=fv*c4.z+iv*gv; cn.z=cc; hn.z=ov*tanhf(cc);
    iv=1.f/(1.f+expf(-i4.w)); fv=1.f/(1.f+expf(-f4.w)); gv=tanhf(g4.w); ov=1.f/(1.f+expf(-o4.w));
    cc=fv*c4.w+iv*gv; cn.w=cc; hn.w=ov*tanhf(cc);
}

// ============================================================================
// Fused LSTM layer-step GEMM + epilogue.
// Tile ti covers hidden units ti*16..+15 as 64 gate-interleaved columns.
// mode 0: layer0 only (grid 32x12); mode 1: layer1 only (grid 32x16);
// mode 2: pair = layer1(step s, p1) [y<16] + layer0(step s+1, p0) [y>=16].
// Last block per tile sums partials in fixed y order, applies activations,
// writes h/c at parity p (inputs read at parity p^1).
// ============================================================================
__global__ void __launch_bounds__(128) gates_fused(
    const float* __restrict__ Wih0, const float* __restrict__ Whh0,
    const float* __restrict__ bih0_, const float* __restrict__ bhh0_,
    const float* __restrict__ Wih1, const float* __restrict__ Whh1,
    const float* __restrict__ bih1_, const float* __restrict__ bhh1_,
    const float* __restrict__ emb, const int* __restrict__ toks,
    int use_xtok, int mode, int p0, int p1)
{
    __shared__ __align__(16) float Ws[2][8][72];
    __shared__ __align__(16) float Xs[2][8][72];
    __shared__ int stoks[64];
    __shared__ int s_last;

    int tid = threadIdx.x, ti = blockIdx.x, y = blockIdx.y;
    int layer = (mode == 2) ? (y < 16 ? 1 : 0) : mode;
    if (mode == 2 && layer == 0) y -= 16;
    int p = layer ? p1 : p0;

    const float *Wih, *Whh, *bih, *bhh, *Xih;
    int Kih, nih, nsplit, ldXih, IHS;
    float *parts; int *cnt;
    const float *hprev, *cprev; float *hout, *cout;
    if (layer == 0) {
        Wih=Wih0; Whh=Whh0; bih=bih0_; bhh=bhh0_;
        Kih=EMBD; nih=4; IHS=56; nsplit=12;
        Xih=emb; ldXih=EMBD;
        parts=g_gp0; cnt=g_cnt0;
        hprev=g_h0f+(p^1)*SB; cprev=g_c0f+(p^1)*SB;
        hout =g_h0f+p*SB;     cout =g_c0f+p*SB;
    } else {
        Wih=Wih1; Whh=Whh1; bih=bih1_; bhh=bhh1_;
        Kih=HID; nih=8; IHS=64; nsplit=16;
        Xih=g_h0f+p1*SB; ldXih=HID;
        parts=g_gp1; cnt=g_cnt1;
        hprev=g_h1f+(p^1)*SB; cprev=g_c1f+(p^1)*SB;
        hout =g_h1f+p*SB;     cout =g_c1f+p*SB;
    }

    const float *W, *X; int ldW, ldX, kbeg, kend;
    int isih = (y < nih);
    if (isih) {
        W=Wih; ldW=Kih; kbeg=y*IHS; kend=kbeg+IHS; if (kend>Kih) kend=Kih;
        X=Xih; ldX=ldXih;
    } else {
        W=Whh; ldW=HID; kbeg=(y-nih)*64; kend=kbeg+64;
        X=hprev; ldX=HID;
    }
    int gath = (layer == 0) && isih;
    if (tid < 64)
        stoks[tid] = gath ? (use_xtok ? g_xtok[tid] : toks[tid]) : tid;
    __syncthreads();

    int l = tid & 31, w = tid >> 5;
    int rg = (w & 1)*8 + (l & 7);     // batch rows rg*4..+3
    int cg = (w >> 1)*4 + (l >> 3);   // cols cg*8..+7
    int wj = tid >> 1, wk = (tid & 1)*4;
    int jr = (wj >> 4)*512 + ti*16 + (wj & 15);  // gate-interleaved W row

    ull acc[4][4];
    #pragma unroll
    for (int r = 0; r < 4; ++r)
        #pragma unroll
        for (int u = 0; u < 4; ++u) acc[r][u] = 0ULL;

    const float* Wp = W + (size_t)jr*ldW + wk;
    const float* Xp = X + (size_t)stoks[wj]*ldX + wk;
    int nch = (kend - kbeg) >> 3;

    float4 wv = *(const float4*)&Wp[kbeg];
    float4 xv = *(const float4*)&Xp[kbeg];
    Ws[0][wk+0][wj]=wv.x; Ws[0][wk+1][wj]=wv.y; Ws[0][wk+2][wj]=wv.z; Ws[0][wk+3][wj]=wv.w;
    Xs[0][wk+0][wj]=xv.x; Xs[0][wk+1][wj]=xv.y; Xs[0][wk+2][wj]=xv.z; Xs[0][wk+3][wj]=xv.w;
    __syncthreads();
    if (nch > 1) {
        wv = *(const float4*)&Wp[kbeg+8];
        xv = *(const float4*)&Xp[kbeg+8];
    }

    for (int c = 0; c < nch; ++c) {
        int cb = c & 1;
        if (c + 1 < nch) {
            int nb = cb ^ 1;
            Ws[nb][wk+0][wj]=wv.x; Ws[nb][wk+1][wj]=wv.y;
            Ws[nb][wk+2][wj]=wv.z; Ws[nb][wk+3][wj]=wv.w;
            Xs[nb][wk+0][wj]=xv.x; Xs[nb][wk+1][wj]=xv.y;
            Xs[nb][wk+2][wj]=xv.z; Xs[nb][wk+3][wj]=xv.w;
        }
        if (c + 2 < nch) {
            int k0 = kbeg + (c+2)*8;
            wv = *(const float4*)&Wp[k0];
            xv = *(const float4*)&Xp[k0];
        }
        #pragma unroll
        for (int q = 0; q < 8; ++q) {
            float4 x4 = *(const float4*)&Xs[cb][q][rg*4];
            ull w0 = *(const ull*)&Ws[cb][q][cg*8];
            ull w1 = *(const ull*)&Ws[cb][q][cg*8+2];
            ull w2 = *(const ull*)&Ws[cb][q][cg*8+4];
            ull w3 = *(const ull*)&Ws[cb][q][cg*8+6];
            ull xr;
            xr = pack2(x4.x, x4.x);
            acc[0][0]=ffma2(xr,w0,acc[0][0]); acc[0][1]=ffma2(xr,w1,acc[0][1]);
            acc[0][2]=ffma2(xr,w2,acc[0][2]); acc[0][3]=ffma2(xr,w3,acc[0][3]);
            xr = pack2(x4.y, x4.y);
            acc[1][0]=ffma2(xr,w0,acc[1][0]); acc[1][1]=ffma2(xr,w1,acc[1][1]);
            acc[1][2]=ffma2(xr,w2,acc[1][2]); acc[1][3]=ffma2(xr,w3,acc[1][3]);
            xr = pack2(x4.z, x4.z);
            acc[2][0]=ffma2(xr,w0,acc[2][0]); acc[2][1]=ffma2(xr,w1,acc[2][1]);
            acc[2][2]=ffma2(xr,w2,acc[2][2]); acc[2][3]=ffma2(xr,w3,acc[2][3]);
            xr = pack2(x4.w, x4.w);
            acc[3][0]=ffma2(xr,w0,acc[3][0]); acc[3][1]=ffma2(xr,w1,acc[3][1]);
            acc[3][2]=ffma2(xr,w2,acc[3][2]); acc[3][3]=ffma2(xr,w3,acc[3][3]);
        }
        __syncthreads();
    }

    // store partials: parts[y][ti][b][64]
    #pragma unroll
    for (int r = 0; r < 4; ++r) {
        int b = rg*4 + r;
        float2 q0 = unpk(acc[r][0]), q1 = unpk(acc[r][1]);
        float2 q2 = unpk(acc[r][2]), q3 = unpk(acc[r][3]);
        float* dst = parts + (((size_t)y*32 + ti)*64 + b)*64 + cg*8;
        *(float4*)dst       = make_float4(q0.x, q0.y, q1.x, q1.y);
        *(float4*)(dst + 4) = make_float4(q2.x, q2.y, q3.x, q3.y);
    }

    __threadfence();
    __syncthreads();
    if (tid == 0) {
        int old = atomicAdd(&cnt[ti], 1);
        s_last = (old == nsplit - 1);
    }
    __syncthreads();

    if (s_last) {
        int b = tid >> 1, uh = (tid & 1)*8, hj0 = ti*16;
        float4 sA[4], sB[4];
        #pragma unroll
        for (int g = 0; g < 4; ++g) {
            const float* b1 = bih + g*512 + hj0 + uh;
            const float* b2 = bhh + g*512 + hj0 + uh;
            float4 x1 = *(const float4*)b1, x2 = *(const float4*)b2;
            sA[g] = make_float4(x1.x+x2.x, x1.y+x2.y, x1.z+x2.z, x1.w+x2.w);
            float4 y1 = *(const float4*)(b1+4), y2 = *(const float4*)(b2+4);
            sB[g] = make_float4(y1.x+y2.x, y1.y+y2.y, y1.z+y2.z, y1.w+y2.w);
        }
        for (int y2 = 0; y2 < nsplit; ++y2) {
            const float* base = parts + (((size_t)y2*32 + ti)*64 + b)*64;
            #pragma unroll
            for (int g = 0; g < 4; ++g) {
                float4 v1 = __ldcg((const float4*)(base + g*16 + uh));
                float4 v2 = __ldcg((const float4*)(base + g*16 + uh + 4));
                sA[g].x+=v1.x; sA[g].y+=v1.y; sA[g].z+=v1.z; sA[g].w+=v1.w;
                sB[g].x+=v2.x; sB[g].y+=v2.y; sB[g].z+=v2.z; sB[g].w+=v2.w;
            }
        }
        int idx = b*HID + hj0 + uh;
        float4 c1 = *(const float4*)&cprev[idx];
        float4 c2 = *(const float4*)&cprev[idx+4];
        float4 cn1, hn1, cn2, hn2;
        lstm4(sA[0], sA[1], sA[2], sA[3], c1, cn1, hn1);
        lstm4(sB[0], sB[1], sB[2], sB[3], c2, cn2, hn2);
        *(float4*)&cout[idx]   = cn1;  *(float4*)&cout[idx+4] = cn2;
        *(float4*)&hout[idx]   = hn1;  *(float4*)&hout[idx+4] = hn2;
        if (tid == 0) cnt[ti] = 0;
    }
}

// ============================================================================
// FC + argmax + token select, fully fused. 500 blocks x 256 thr,
// tile 64 vocab x 64 batch, K=512 pipelined. Last block (atomic counter)
// does the deterministic global argmax (ascending, lowest-index ties).
// ============================================================================
__global__ void __launch_bounds__(256) fc_fused(
    const float* __restrict__ fcW, const float* __restrict__ fcb,
    float* __restrict__ out,
    const int* __restrict__ target, const int* __restrict__ tfmask,
    int t, int p1)
{
    __shared__ __align__(16) float Ws[2][16][72];
    __shared__ __align__(16) float Hs[2][16][72];
    __shared__ float rval[BATCH*16];
    __shared__ int   ridx[BATCH*16];
    __shared__ float sv[256];
    __shared__ int   si[256];
    __shared__ int   s_last;

    int tid = threadIdx.x, v0 = blockIdx.x*64;
    int l = tid & 31, w = tid >> 5;
    int rg = (w & 1)*8 + (l & 7);     // batch rows rg*4..+3
    int cg = (w >> 1)*4 + (l >> 3);   // cols cg*4..+3
    int wj = tid >> 2, wk = (tid & 3)*4;

    ull acc[4][2];
    #pragma unroll
    for (int r = 0; r < 4; ++r) { acc[r][0]=0ULL; acc[r][1]=0ULL; }

    const float* h1p = g_h1f + (size_t)p1*SB;
    const float* Wp = fcW + (size_t)(v0 + wj)*HID + wk;
    const float* Hp = h1p + (size_t)wj*HID + wk;

    const int NCH = HID / 16;   // 32

    float4 wa = *(const float4*)&Wp[0];
    float4 ha = *(const float4*)&Hp[0];
    Ws[0][wk+0][wj]=wa.x; Ws[0][wk+1][wj]=wa.y; Ws[0][wk+2][wj]=wa.z; Ws[0][wk+3][wj]=wa.w;
    Hs[0][wk+0][wj]=ha.x; Hs[0][wk+1][wj]=ha.y; Hs[0][wk+2][wj]=ha.z; Hs[0][wk+3][wj]=ha.w;
    __syncthreads();
    wa = *(const float4*)&Wp[16];
    ha = *(const float4*)&Hp[16];

    for (int c = 0; c < NCH; ++c) {
        int cb = c & 1;
        if (c + 1 < NCH) {
            int nb = cb ^ 1;
            Ws[nb][wk+0][wj]=wa.x; Ws[nb][wk+1][wj]=wa.y;
            Ws[nb][wk+2][wj]=wa.z; Ws[nb][wk+3][wj]=wa.w;
            Hs[nb][wk+0][wj]=ha.x; Hs[nb][wk+1][wj]=ha.y;
            Hs[nb][wk+2][wj]=ha.z; Hs[nb][wk+3][wj]=ha.w;
        }
        if (c + 2 < NCH) {
            int k0 = (c+2)*16;
            wa = *(const float4*)&Wp[k0];
            ha = *(const float4*)&Hp[k0];
        }
        #pragma unroll
        for (int q = 0; q < 16; ++q) {
            float4 x4 = *(const float4*)&Hs[cb][q][rg*4];
            ull w0 = *(const ull*)&Ws[cb][q][cg*4];
            ull w1 = *(const ull*)&Ws[cb][q][cg*4+2];
            ull xr;
            xr = pack2(x4.x, x4.x);
            acc[0][0]=ffma2(xr,w0,acc[0][0]); acc[0][1]=ffma2(xr,w1,acc[0][1]);
            xr = pack2(x4.y, x4.y);
            acc[1][0]=ffma2(xr,w0,acc[1][0]); acc[1][1]=ffma2(xr,w1,acc[1][1]);
            xr = pack2(x4.z, x4.z);
            acc[2][0]=ffma2(xr,w0,acc[2][0]); acc[2][1]=ffma2(xr,w1,acc[2][1]);
            xr = pack2(x4.w, x4.w);
            acc[3][0]=ffma2(xr,w0,acc[3][0]); acc[3][1]=ffma2(xr,w1,acc[3][1]);
        }
        __syncthreads();
    }

    float4 bv = *(const float4*)&fcb[v0 + cg*4];

    #pragma unroll
    for (int r = 0; r < 4; ++r) {
        int b = rg*4 + r;
        float2 t0 = unpk(acc[r][0]), t1 = unpk(acc[r][1]);
        float v_0 = t0.x + bv.x, v_1 = t0.y + bv.y;
        float v_2 = t1.x + bv.z, v_3 = t1.y + bv.w;
        *(float4*)(out + (size_t)b*VOCAB + v0 + cg*4) = make_float4(v_0, v_1, v_2, v_3);
        float best = v_0; int bi = 0;
        if (v_1 > best) { best = v_1; bi = 1; }
        if (v_2 > best) { best = v_2; bi = 2; }
        if (v_3 > best) { best = v_3; bi = 3; }
        rval[b*16 + cg] = best;
        ridx[b*16 + cg] = v0 + cg*4 + bi;
    }
    __syncthreads();
    if (tid < BATCH) {
        float best = rval[tid*16]; int bi = ridx[tid*16];
        #pragma unroll
        for (int u = 1; u < 16; ++u) {
            float v = rval[tid*16 + u];
            if (v > best) { best = v; bi = ridx[tid*16 + u]; }
        }
        g_pval[blockIdx.x*BATCH + tid] = best;
        g_pidx[blockIdx.x*BATCH + tid] = bi;
    }

    __threadfence();
    __syncthreads();
    if (tid == 0) {
        int old = atomicAdd(&g_cntFC, 1);
        s_last = (old == (int)gridDim.x - 1);
    }
    __syncthreads();

    if (s_last) {
        int b = tid >> 2, seg = tid & 3;
        const int per = FCBLK / 4;  // 125
        int q0 = seg*per;
        float best = -3.4e38f; int bi = 0;
        for (int q = q0; q < q0 + per; ++q) {
            float v = __ldcg(&g_pval[q*BATCH + b]);
            if (v > best) { best = v; bi = __ldcg(&g_pidx[q*BATCH + b]); }
        }
        sv[tid] = best; si[tid] = bi;
        __syncthreads();
        if (seg == 0) {
            #pragma unroll
            for (int u = 1; u < 4; ++u) {
                float v = sv[tid + u];
                if (v > best) { best = v; bi = si[tid + u]; }
            }
            g_xtok[b] = (tfmask[t] > 0) ? target[t*BATCH + b] : bi;
        }
        if (tid == 0) g_cntFC = 0;
    }
}

extern "C" void kernel_launch(void* const* d_in, const int* in_sizes, int n_in,
                              void* d_out, int out_size)
{
    const float *enc_embed,*dec_embed,*fcW,*fcb;
    const float *eWih0,*eWhh0,*ebih0,*ebhh0,*eWih1,*eWhh1,*ebih1,*ebhh1;
    const float *dWih0,*dWhh0,*dbih0,*dbhh0,*dWih1,*dWhh1,*dbih1,*dbhh1;
    const int *src,*target,*tfmask;

    if (in_sizes[0] == SRCLEN*BATCH) {
        src=(const int*)d_in[0]; target=(const int*)d_in[1]; tfmask=(const int*)d_in[2];
        enc_embed=(const float*)d_in[3]; dec_embed=(const float*)d_in[4];
        eWih0=(const float*)d_in[5];  eWhh0=(const float*)d_in[6];
        ebih0=(const float*)d_in[7];  ebhh0=(const float*)d_in[8];
        eWih1=(const float*)d_in[9];  eWhh1=(const float*)d_in[10];
        ebih1=(const float*)d_in[11]; ebhh1=(const float*)d_in[12];
        dWih0=(const float*)d_in[13]; dWhh0=(const float*)d_in[14];
        dbih0=(const float*)d_in[15]; dbhh0=(const float*)d_in[16];
        dWih1=(const float*)d_in[17]; dWhh1=(const float*)d_in[18];
        dbih1=(const float*)d_in[19]; dbhh1=(const float*)d_in[20];
        fcW=(const float*)d_in[21];   fcb=(const float*)d_in[22];
    } else {
        enc_embed=(const float*)d_in[0];
        eWih0=(const float*)d_in[1];  eWhh0=(const float*)d_in[2];
        ebih0=(const float*)d_in[3];  ebhh0=(const float*)d_in[4];
        eWih1=(const float*)d_in[5];  eWhh1=(const float*)d_in[6];
        ebih1=(const float*)d_in[7];  ebhh1=(const float*)d_in[8];
        dec_embed=(const float*)d_in[9];
        dWih0=(const float*)d_in[10]; dWhh0=(const float*)d_in[11];
        dbih0=(const float*)d_in[12]; dbhh0=(const float*)d_in[13];
        dWih1=(const float*)d_in[14]; dWhh1=(const float*)d_in[15];
        dbih1=(const float*)d_in[16]; dbhh1=(const float*)d_in[17];
        fcW=(const float*)d_in[18];   fcb=(const float*)d_in[19];
        src=(const int*)d_in[20]; target=(const int*)d_in[21]; tfmask=(const int*)d_in[22];
    }

    float* out = (float*)d_out;
    cudaMemsetAsync(out, 0, (size_t)BATCH * VOCAB * sizeof(float));
    init_kernel<<<64, 256>>>(target);

    // ---- encoder, software-pipelined across layers ----
    // L0(0)
    gates_fused<<<dim3(32,12),128>>>(eWih0,eWhh0,ebih0,ebhh0, eWih1,eWhh1,ebih1,ebhh1,
                                     enc_embed, src, 0, /*mode*/0, /*p0*/0, /*p1*/0);
    // pair(s) = L1(s) + L0(s+1), s = 0..62
    for (int s = 0; s < SRCLEN-1; ++s) {
        gates_fused<<<dim3(32,28),128>>>(eWih0,eWhh0,ebih0,ebhh0, eWih1,eWhh1,ebih1,ebhh1,
                                         enc_embed, src + (s+1)*BATCH, 0,
                                         /*mode*/2, /*p0*/(s+1)&1, /*p1*/s&1);
    }
    // L1(63)
    gates_fused<<<dim3(32,16),128>>>(eWih0,eWhh0,ebih0,ebhh0, eWih1,eWhh1,ebih1,ebhh1,
                                     enc_embed, src, 0, /*mode*/1, /*p0*/0, /*p1*/(SRCLEN-1)&1);

    // ---- decoder ----
    for (int t = 1; t < TGTLEN; ++t) {
        int p = (SRCLEN - 1 + t) & 1;
        gates_fused<<<dim3(32,12),128>>>(dWih0,dWhh0,dbih0,dbhh0, dWih1,dWhh1,dbih1,dbhh1,
                                         dec_embed, src, /*use_xtok*/1, /*mode*/0, p, p);
        gates_fused<<<dim3(32,16),128>>>(dWih0,dWhh0,dbih0,dbhh0, dWih1,dWhh1,dbih1,dbhh1,
                                         dec_embed, src, 0, /*mode*/1, p, p);
        fc_fused<<<FCBLK,256>>>(fcW, fcb, out + (size_t)t*BATCH*VOCAB,
                                target, tfmask, t, p);
    }
}

// round 13
// speedup vs baseline: 1.2454x; 1.2303x over previous
#include <cuda_runtime.h>
#include <math.h>

#define BATCH  64
#define HID    512
#define EMBD   200
#define VOCAB  32000
#define SRCLEN 64
#define TGTLEN 64
#define NBLK   148
#define NTHR   256
#define SB     (BATCH*HID)
#define PARTSZ (BATCH*2048)
#define FCT    500

typedef unsigned long long ull;

__device__ __forceinline__ ull pack2(float a, float b) {
    ull r; asm("mov.b64 %0, {%1,%2};" : "=l"(r) : "f"(a), "f"(b)); return r;
}
__device__ __forceinline__ ull ffma2(ull a, ull b, ull c) {
    ull d; asm("fma.rn.f32x2 %0, %1, %2, %3;" : "=l"(d) : "l"(a), "l"(b), "l"(c)); return d;
}
__device__ __forceinline__ float2 unpk(ull v) {
    float2 r; asm("mov.b64 {%0,%1}, %2;" : "=f"(r.x), "=f"(r.y) : "l"(v)); return r;
}

__device__ __align__(16) float g_parts0[4*PARTSZ];
__device__ __align__(16) float g_parts1[4*PARTSZ];
__device__ __align__(16) float g_h0[SB], g_c0[SB], g_h1[SB], g_c1[SB];
__device__ __align__(16) float g_bsum[4*2048];
__device__ int g_xtok[BATCH];
__device__ __align__(16) float g_pval[512*BATCH];
__device__ int g_pidx[512*BATCH];
__device__ unsigned g_barcnt;
__device__ volatile unsigned g_bargen;

__device__ __forceinline__ void gridbar() {
    __syncthreads();
    if (threadIdx.x == 0) {
        __threadfence();
        unsigned gen = g_bargen;
        if (atomicAdd(&g_barcnt, 1u) == NBLK - 1u) {
            g_barcnt = 0u;
            __threadfence();
            g_bargen = gen + 1u;
        } else {
            while (g_bargen == gen) __nanosleep(64);
            __threadfence();
        }
    }
    __syncthreads();
}

// 64x64 tile: acc[b 4][c 2x2] += sum_k X[rows[b]][k]*W[c][k], k in [kbeg,kend)
__device__ __forceinline__ void gemm_tile(
    const float* __restrict__ W, int ldW,
    const float* __restrict__ X, int ldX,
    const int* rows, int kbeg, int kend,
    float* Ws, float* Xs, ull acc[4][2])
{
    int tid = threadIdx.x;
    int sj = tid >> 2, sk = (tid & 3) << 2;
    int rg = tid >> 4, cg = tid & 15;
    const float* Wp = W + (size_t)sj*ldW;
    const float* Xp = X + (size_t)rows[sj]*ldX;
    int nch = (kend - kbeg + 15) >> 4;
    float4 wv, xv;
    int kg = kbeg + sk;
    if (kg + 4 <= kend) { wv = *(const float4*)&Wp[kg]; xv = __ldcg((const float4*)&Xp[kg]); }
    else wv = xv = make_float4(0.f,0.f,0.f,0.f);
    {
        float* w_ = Ws + sk*68 + sj; float* x_ = Xs + sk*68 + sj;
        w_[0]=wv.x; w_[68]=wv.y; w_[136]=wv.z; w_[204]=wv.w;
        x_[0]=xv.x; x_[68]=xv.y; x_[136]=xv.z; x_[204]=xv.w;
    }
    __syncthreads();
    if (nch > 1) {
        kg = kbeg + 16 + sk;
        if (kg + 4 <= kend) { wv = *(const float4*)&Wp[kg]; xv = __ldcg((const float4*)&Xp[kg]); }
        else wv = xv = make_float4(0.f,0.f,0.f,0.f);
    }
    for (int c = 0; c < nch; ++c) {
        int cb = c & 1;
        if (c + 1 < nch) {
            float* w_ = Ws + (cb^1)*1088 + sk*68 + sj;
            float* x_ = Xs + (cb^1)*1088 + sk*68 + sj;
            w_[0]=wv.x; w_[68]=wv.y; w_[136]=wv.z; w_[204]=wv.w;
            x_[0]=xv.x; x_[68]=xv.y; x_[136]=xv.z; x_[204]=xv.w;
        }
        if (c + 2 < nch) {
            kg = kbeg + (c+2)*16 + sk;
            if (kg + 4 <= kend) { wv = *(const float4*)&Wp[kg]; xv = __ldcg((const float4*)&Xp[kg]); }
            else wv = xv = make_float4(0.f,0.f,0.f,0.f);
        }
        const float* Wb = Ws + cb*1088;
        const float* Xb = Xs + cb*1088;
        #pragma unroll
        for (int q = 0; q < 16; ++q) {
            float4 x4 = *(const float4*)&Xb[q*68 + (rg<<2)];
            float4 w4 = *(const float4*)&Wb[q*68 + (cg<<2)];
            ull w0 = pack2(w4.x, w4.y), w1 = pack2(w4.z, w4.w), xr;
            xr = pack2(x4.x,x4.x); acc[0][0]=ffma2(xr,w0,acc[0][0]); acc[0][1]=ffma2(xr,w1,acc[0][1]);
            xr = pack2(x4.y,x4.y); acc[1][0]=ffma2(xr,w0,acc[1][0]); acc[1][1]=ffma2(xr,w1,acc[1][1]);
            xr = pack2(x4.z,x4.z); acc[2][0]=ffma2(xr,w0,acc[2][0]); acc[2][1]=ffma2(xr,w1,acc[2][1]);
            xr = pack2(x4.w,x4.w); acc[3][0]=ffma2(xr,w0,acc[3][0]); acc[3][1]=ffma2(xr,w1,acc[3][1]);
        }
        __syncthreads();
    }
}

// one gates K-split job: job = ks*32 + ti (ti = 64-col tile of 2048)
__device__ __forceinline__ void gates_job(
    int job, int layer,
    const float* __restrict__ Wih, const float* __restrict__ Whh,
    const float* __restrict__ xsrc, const int* __restrict__ toks,
    const float* __restrict__ hprev, float* __restrict__ parts,
    float* Ws, float* Xs, int* s_rows)
{
    int ks = job >> 5, ti = job & 31, tid = threadIdx.x;
    const float *W, *X; int ldW, ldX, kbeg, kend, gather;
    if (ks < 2) {
        ldW = (layer == 0) ? EMBD : HID;
        W = Wih; X = xsrc; ldX = ldW;
        if (layer == 0) { kbeg = ks ? 112 : 0; kend = ks ? 200 : 112; }
        else            { kbeg = ks*256; kend = kbeg + 256; }
        gather = (layer == 0);
    } else {
        W = Whh; ldW = HID; X = hprev; ldX = HID;
        kbeg = (ks-2)*256; kend = kbeg + 256; gather = 0;
    }
    __syncthreads();
    if (tid < 64) s_rows[tid] = gather ? __ldcg(&toks[tid]) : tid;
    __syncthreads();
    ull acc[4][2] = {{0,0},{0,0},{0,0},{0,0}};
    gemm_tile(W + (size_t)(ti*64)*ldW, ldW, X, ldX, s_rows, kbeg, kend, Ws, Xs, acc);
    int rg = tid >> 4, cg = tid & 15;
    #pragma unroll
    for (int r = 0; r < 4; ++r) {
        float2 a = unpk(acc[r][0]), b = unpk(acc[r][1]);
        *(float4*)&parts[(size_t)ks*PARTSZ + (size_t)(rg*4+r)*2048 + ti*64 + cg*4] =
            make_float4(a.x, a.y, b.x, b.y);
    }
}

__device__ __forceinline__ void epi_elem(int e, const float* __restrict__ bsum,
                                         const float* __restrict__ parts,
                                         float* __restrict__ h, float* __restrict__ c)
{
    int b = e >> 9, j = e & 511;
    float s[4];
    #pragma unroll
    for (int g = 0; g < 4; ++g) {
        int col = (g << 9) + j;
        float v = bsum[col];
        #pragma unroll
        for (int ks = 0; ks < 4; ++ks)
            v += __ldcg(&parts[(size_t)ks*PARTSZ + (size_t)b*2048 + col]);
        s[g] = v;
    }
    float iv = 1.f/(1.f+expf(-s[0])), fv = 1.f/(1.f+expf(-s[1]));
    float gv = tanhf(s[2]),           ov = 1.f/(1.f+expf(-s[3]));
    float cn = fv*__ldcg(&c[e]) + iv*gv;
    c[e] = cn;
    h[e] = ov*tanhf(cn);
}

__device__ __forceinline__ void fc_job(
    int vt, const float* __restrict__ fcW, const float* __restrict__ fcb,
    float* __restrict__ out, float* Ws, float* Xs, int* s_rows,
    float* s_red, int* s_redi)
{
    int tid = threadIdx.x;
    __syncthreads();
    if (tid < 64) s_rows[tid] = tid;
    __syncthreads();
    ull acc[4][2] = {{0,0},{0,0},{0,0},{0,0}};
    gemm_tile(fcW + (size_t)(vt*64)*HID, HID, g_h1, HID, s_rows, 0, HID, Ws, Xs, acc);
    int rg = tid >> 4, cg = tid & 15, v0 = vt*64;
    float4 bv = *(const float4*)&fcb[v0 + cg*4];
    #pragma unroll
    for (int r = 0; r < 4; ++r) {
        int b = rg*4 + r;
        float2 a = unpk(acc[r][0]), d = unpk(acc[r][1]);
        float v_0 = a.x+bv.x, v_1 = a.y+bv.y, v_2 = d.x+bv.z, v_3 = d.y+bv.w;
        *(float4*)&out[(size_t)b*VOCAB + v0 + cg*4] = make_float4(v_0, v_1, v_2, v_3);
        float best = v_0; int bi = 0;
        if (v_1 > best) { best = v_1; bi = 1; }
        if (v_2 > best) { best = v_2; bi = 2; }
        if (v_3 > best) { best = v_3; bi = 3; }
        s_red[b*16 + cg] = best; s_redi[b*16 + cg] = v0 + cg*4 + bi;
    }
    __syncthreads();
    if (tid < 64) {
        float best = s_red[tid*16]; int bi = s_redi[tid*16];
        #pragma unroll
        for (int u = 1; u < 16; ++u) {
            float v = s_red[tid*16 + u];
            if (v > best) { best = v; bi = s_redi[tid*16 + u]; }
        }
        g_pval[vt*BATCH + tid] = best;
        g_pidx[vt*BATCH + tid] = bi;
    }
}

__global__ void __launch_bounds__(NTHR, 1) seq2seq_all(
    const float* __restrict__ enc_embed,
    const float* __restrict__ eWih0, const float* __restrict__ eWhh0,
    const float* __restrict__ ebih0, const float* __restrict__ ebhh0,
    const float* __restrict__ eWih1, const float* __restrict__ eWhh1,
    const float* __restrict__ ebih1, const float* __restrict__ ebhh1,
    const float* __restrict__ dec_embed,
    const float* __restrict__ dWih0, const float* __restrict__ dWhh0,
    const float* __restrict__ dbih0, const float* __restrict__ dbhh0,
    const float* __restrict__ dWih1, const float* __restrict__ dWhh1,
    const float* __restrict__ dbih1, const float* __restrict__ dbhh1,
    const float* __restrict__ fcW, const float* __restrict__ fcb,
    const int* __restrict__ src, const int* __restrict__ target,
    const int* __restrict__ tfmask, float* __restrict__ out)
{
    __shared__ __align__(16) float Ws[2*1088];
    __shared__ __align__(16) float Xs[2*1088];
    __shared__ int   s_rows[64];
    __shared__ float s_red[1024];
    __shared__ int   s_redi[1024];

    int bid = blockIdx.x, tid = threadIdx.x;
    int gtid = bid*NTHR + tid;
    const int GSTR = NBLK*NTHR;

    for (int e = gtid; e < SB; e += GSTR) { g_h0[e]=0.f; g_c0[e]=0.f; g_h1[e]=0.f; g_c1[e]=0.f; }
    for (int e = gtid; e < 2048; e += GSTR) {
        g_bsum[e]      = ebih0[e] + ebhh0[e];
        g_bsum[2048+e] = ebih1[e] + ebhh1[e];
        g_bsum[4096+e] = dbih0[e] + dbhh0[e];
        g_bsum[6144+e] = dbih1[e] + dbhh1[e];
    }
    if (gtid < BATCH) g_xtok[gtid] = target[gtid];
    gridbar();

    // ---- encoder ----
    for (int job = bid; job < 128; job += NBLK)
        gates_job(job, 0, eWih0, eWhh0, enc_embed, src, g_h0, g_parts0, Ws, Xs, s_rows);
    gridbar();
    for (int e = gtid; e < SB; e += GSTR) epi_elem(e, g_bsum, g_parts0, g_h0, g_c0);
    gridbar();
    for (int s = 0; s < SRCLEN-1; ++s) {
        for (int job = bid; job < 256; job += NBLK) {
            if (job < 128)
                gates_job(job, 1, eWih1, eWhh1, g_h0, (const int*)0, g_h1, g_parts1, Ws, Xs, s_rows);
            else
                gates_job(job-128, 0, eWih0, eWhh0, enc_embed, src + (s+1)*BATCH, g_h0, g_parts0, Ws, Xs, s_rows);
        }
        gridbar();
        for (int e = gtid; e < 2*SB; e += GSTR) {
            if (e < SB) epi_elem(e,    g_bsum+2048, g_parts1, g_h1, g_c1);
            else        epi_elem(e-SB, g_bsum,      g_parts0, g_h0, g_c0);
        }
        gridbar();
    }
    for (int job = bid; job < 128; job += NBLK)
        gates_job(job, 1, eWih1, eWhh1, g_h0, (const int*)0, g_h1, g_parts1, Ws, Xs, s_rows);
    gridbar();
    for (int e = gtid; e < SB; e += GSTR) epi_elem(e, g_bsum+2048, g_parts1, g_h1, g_c1);
    gridbar();

    // ---- decoder ----
    for (int t = 1; t < TGTLEN; ++t) {
        for (int job = bid; job < 128; job += NBLK)
            gates_job(job, 0, dWih0, dWhh0, dec_embed, g_xtok, g_h0, g_parts0, Ws, Xs, s_rows);
        gridbar();
        for (int e = gtid; e < SB; e += GSTR) epi_elem(e, g_bsum+4096, g_parts0, g_h0, g_c0);
        gridbar();
        for (int job = bid; job < 128; job += NBLK)
            gates_job(job, 1, dWih1, dWhh1, g_h0, (const int*)0, g_h1, g_parts1, Ws, Xs, s_rows);
        gridbar();
        for (int e = gtid; e < SB; e += GSTR) epi_elem(e, g_bsum+6144, g_parts1, g_h1, g_c1);
        gridbar();

        float* outT = out + (size_t)t*BATCH*VOCAB;
        for (int vt = bid; vt < FCT; vt += NBLK)
            fc_job(vt, fcW, fcb, outT, Ws, Xs, s_rows, s_red, s_redi);
        gridbar();

        if (bid < BATCH) {
            int b = bid;
            int q0 = tid*2;
            float best = -3.4e38f; int bi = 0;
            #pragma unroll
            for (int q = q0; q < q0+2; ++q) {
                if (q < FCT) {
                    float v = __ldcg(&g_pval[q*BATCH + b]);
                    if (v > best) { best = v; bi = __ldcg(&g_pidx[q*BATCH + b]); }
                }
            }
            s_red[tid] = best; s_redi[tid] = bi;
            __syncthreads();
            if (tid == 0) {
                for (int u = 1; u < 256; ++u)
                    if (s_red[u] > best) { best = s_red[u]; bi = s_redi[u]; }
                g_xtok[b] = (tfmask[t] > 0) ? target[t*BATCH + b] : bi;
            }
        }
        gridbar();
    }
}

extern "C" void kernel_launch(void* const* d_in, const int* in_sizes, int n_in,
                              void* d_out, int out_size)
{
    const float *ee,*de,*fw,*fb;
    const float *a1,*a2,*a3,*a4,*a5,*a6,*a7,*a8;
    const float *b1,*b2,*b3,*b4,*b5,*b6,*b7,*b8;
    const int *src,*tgt,*tfm;
    if (in_sizes[0] == SRCLEN*BATCH) {
        src=(const int*)d_in[0]; tgt=(const int*)d_in[1]; tfm=(const int*)d_in[2];
        ee=(const float*)d_in[3]; de=(const float*)d_in[4];
        a1=(const float*)d_in[5];  a2=(const float*)d_in[6];  a3=(const float*)d_in[7];  a4=(const float*)d_in[8];
        a5=(const float*)d_in[9];  a6=(const float*)d_in[10]; a7=(const float*)d_in[11]; a8=(const float*)d_in[12];
        b1=(const float*)d_in[13]; b2=(const float*)d_in[14]; b3=(const float*)d_in[15]; b4=(const float*)d_in[16];
        b5=(const float*)d_in[17]; b6=(const float*)d_in[18]; b7=(const float*)d_in[19]; b8=(const float*)d_in[20];
        fw=(const float*)d_in[21]; fb=(const float*)d_in[22];
    } else {
        ee=(const float*)d_in[0];
        a1=(const float*)d_in[1];  a2=(const float*)d_in[2];  a3=(const float*)d_in[3];  a4=(const float*)d_in[4];
        a5=(const float*)d_in[5];  a6=(const float*)d_in[6];  a7=(const float*)d_in[7];  a8=(const float*)d_in[8];
        de=(const float*)d_in[9];
        b1=(const float*)d_in[10]; b2=(const float*)d_in[11]; b3=(const float*)d_in[12]; b4=(const float*)d_in[13];
        b5=(const float*)d_in[14]; b6=(const float*)d_in[15]; b7=(const float*)d_in[16]; b8=(const float*)d_in[17];
        fw=(const float*)d_in[18]; fb=(const float*)d_in[19];
        src=(const int*)d_in[20]; tgt=(const int*)d_in[21]; tfm=(const int*)d_in[22];
    }
    float* out = (float*)d_out;
    cudaMemsetAsync(out, 0, (size_t)BATCH*VOCAB*sizeof(float));
    seq2seq_all<<<NBLK, NTHR>>>(ee, a1,a2,a3,a4, a5,a6,a7,a8,
                                de, b1,b2,b3,b4, b5,b6,b7,b8,
                                fw, fb, src, tgt, tfm, out);
}

// round 14
// speedup vs baseline: 1.3859x; 1.1128x over previous
#include <cuda_runtime.h>
#include <math.h>

#define BATCH  64
#define HID    512
#define EMBD   200
#define VOCAB  32000
#define SRCLEN 64
#define TGTLEN 64
#define NBLK   296
#define NTHR   256
#define SB     (BATCH*HID)
#define PARTSZ (BATCH*2048)
#define NSPL   8
#define FCT    500

typedef unsigned long long ull;

__device__ __forceinline__ ull pack2(float a, float b) {
    ull r; asm("mov.b64 %0, {%1,%2};" : "=l"(r) : "f"(a), "f"(b)); return r;
}
__device__ __forceinline__ ull ffma2(ull a, ull b, ull c) {
    ull d; asm("fma.rn.f32x2 %0, %1, %2, %3;" : "=l"(d) : "l"(a), "l"(b), "l"(c)); return d;
}
__device__ __forceinline__ float2 unpk(ull v) {
    float2 r; asm("mov.b64 {%0,%1}, %2;" : "=f"(r.x), "=f"(r.y) : "l"(v)); return r;
}

__device__ __align__(16) float g_parts0[NSPL*PARTSZ];
__device__ __align__(16) float g_parts1[NSPL*PARTSZ];
__device__ __align__(16) float g_h0[SB], g_c0[SB], g_h1[SB], g_c1[SB];
__device__ __align__(16) float g_bsum[4*2048];
__device__ int g_xtok[BATCH];
__device__ __align__(16) float g_pval[512*BATCH];
__device__ int g_pidx[512*BATCH];
__device__ unsigned g_barcnt;
__device__ volatile unsigned g_bargen;

__device__ __forceinline__ void gridbar() {
    __syncthreads();
    if (threadIdx.x == 0) {
        __threadfence();
        unsigned gen = g_bargen;
        if (atomicAdd(&g_barcnt, 1u) == NBLK - 1u) {
            g_barcnt = 0u;
            __threadfence();
            g_bargen = gen + 1u;
        } else {
            while (g_bargen == gen) __nanosleep(64);
            __threadfence();
        }
    }
    __syncthreads();
}

// 64x64 tile: acc[b 4][c 2x2] += sum_k X[rows[b]][k]*W[c][k], k in [kbeg,kend)
__device__ __forceinline__ void gemm_tile(
    const float* __restrict__ W, int ldW,
    const float* __restrict__ X, int ldX,
    const int* rows, int kbeg, int kend,
    float* Ws, float* Xs, ull acc[4][2])
{
    int tid = threadIdx.x;
    int sj = tid >> 2, sk = (tid & 3) << 2;
    int rg = tid >> 4, cg = tid & 15;
    const float* Wp = W + (size_t)sj*ldW;
    const float* Xp = X + (size_t)rows[sj]*ldX;
    int nch = (kend - kbeg + 15) >> 4;
    float4 wv, xv;
    int kg = kbeg + sk;
    if (kg + 4 <= kend) { wv = *(const float4*)&Wp[kg]; xv = __ldcg((const float4*)&Xp[kg]); }
    else wv = xv = make_float4(0.f,0.f,0.f,0.f);
    {
        float* w_ = Ws + sk*68 + sj; float* x_ = Xs + sk*68 + sj;
        w_[0]=wv.x; w_[68]=wv.y; w_[136]=wv.z; w_[204]=wv.w;
        x_[0]=xv.x; x_[68]=xv.y; x_[136]=xv.z; x_[204]=xv.w;
    }
    __syncthreads();
    if (nch > 1) {
        kg = kbeg + 16 + sk;
        if (kg + 4 <= kend) { wv = *(const float4*)&Wp[kg]; xv = __ldcg((const float4*)&Xp[kg]); }
        else wv = xv = make_float4(0.f,0.f,0.f,0.f);
    }
    for (int c = 0; c < nch; ++c) {
        int cb = c & 1;
        if (c + 1 < nch) {
            float* w_ = Ws + (cb^1)*1088 + sk*68 + sj;
            float* x_ = Xs + (cb^1)*1088 + sk*68 + sj;
            w_[0]=wv.x; w_[68]=wv.y; w_[136]=wv.z; w_[204]=wv.w;
            x_[0]=xv.x; x_[68]=xv.y; x_[136]=xv.z; x_[204]=xv.w;
        }
        if (c + 2 < nch) {
            kg = kbeg + (c+2)*16 + sk;
            if (kg + 4 <= kend) { wv = *(const float4*)&Wp[kg]; xv = __ldcg((const float4*)&Xp[kg]); }
            else wv = xv = make_float4(0.f,0.f,0.f,0.f);
        }
        const float* Wb = Ws + cb*1088;
        const float* Xb = Xs + cb*1088;
        #pragma unroll
        for (int q = 0; q < 16; ++q) {
            float4 x4 = *(const float4*)&Xb[q*68 + (rg<<2)];
            ulonglong2 w2 = *(const ulonglong2*)&Wb[q*68 + (cg<<2)];
            ull xr;
            xr = pack2(x4.x,x4.x); acc[0][0]=ffma2(xr,w2.x,acc[0][0]); acc[0][1]=ffma2(xr,w2.y,acc[0][1]);
            xr = pack2(x4.y,x4.y); acc[1][0]=ffma2(xr,w2.x,acc[1][0]); acc[1][1]=ffma2(xr,w2.y,acc[1][1]);
            xr = pack2(x4.z,x4.z); acc[2][0]=ffma2(xr,w2.x,acc[2][0]); acc[2][1]=ffma2(xr,w2.y,acc[2][1]);
            xr = pack2(x4.w,x4.w); acc[3][0]=ffma2(xr,w2.x,acc[3][0]); acc[3][1]=ffma2(xr,w2.y,acc[3][1]);
        }
        __syncthreads();
    }
}

// K-split table: 8 splits per layer, bounds multiple of 4
__device__ __forceinline__ void split_range(int layer, int ks, int& isih, int& kbeg, int& kend) {
    if (layer == 0) {
        if (ks < 2) { isih = 1; kbeg = ks ? 112 : 0; kend = ks ? 200 : 112; }
        else {
            isih = 0;
            int h = ks - 2;   // 6 hh splits: 88,88,84,84,84,84
            kbeg = (h < 2) ? h*88 : 176 + (h-2)*84;
            kend = (h < 2) ? kbeg + 88 : kbeg + 84;
        }
    } else {
        isih = (ks < 4);
        kbeg = (ks & 3)*128; kend = kbeg + 128;
    }
}

// one gates job: job = ks*32 + ti (ti = 64-col tile of 2048)
__device__ __forceinline__ void gates_job(
    int job, int layer,
    const float* __restrict__ Wih, const float* __restrict__ Whh,
    const float* __restrict__ xsrc, const int* __restrict__ toks,
    const float* __restrict__ hprev, float* __restrict__ parts,
    float* Ws, float* Xs, int* s_rows)
{
    int ks = job >> 5, ti = job & 31, tid = threadIdx.x;
    int isih, kbeg, kend;
    split_range(layer, ks, isih, kbeg, kend);
    const float *W, *X; int ldW, ldX, gather;
    if (isih) {
        ldW = (layer == 0) ? EMBD : HID;
        W = Wih; X = xsrc; ldX = ldW;
        gather = (layer == 0);
    } else {
        W = Whh; ldW = HID; X = hprev; ldX = HID; gather = 0;
    }
    __syncthreads();
    if (tid < 64) s_rows[tid] = gather ? __ldcg(&toks[tid]) : tid;
    __syncthreads();
    ull acc[4][2] = {{0,0},{0,0},{0,0},{0,0}};
    gemm_tile(W + (size_t)(ti*64)*ldW, ldW, X, ldX, s_rows, kbeg, kend, Ws, Xs, acc);
    int rg = tid >> 4, cg = tid & 15;
    #pragma unroll
    for (int r = 0; r < 4; ++r) {
        float2 a = unpk(acc[r][0]), b = unpk(acc[r][1]);
        *(float4*)&parts[(size_t)ks*PARTSZ + (size_t)(rg*4+r)*2048 + ti*64 + cg*4] =
            make_float4(a.x, a.y, b.x, b.y);
    }
}

__device__ __forceinline__ void epi_elem(int e, const float* __restrict__ bsum,
                                         const float* __restrict__ parts,
                                         float* __restrict__ h, float* __restrict__ c)
{
    int b = e >> 9, j = e & 511;
    float s[4];
    #pragma unroll
    for (int g = 0; g < 4; ++g) {
        int col = (g << 9) + j;
        float v = bsum[col];
        #pragma unroll
        for (int ks = 0; ks < NSPL; ++ks)
            v += __ldcg(&parts[(size_t)ks*PARTSZ + (size_t)b*2048 + col]);
        s[g] = v;
    }
    float iv = 1.f/(1.f+expf(-s[0])), fv = 1.f/(1.f+expf(-s[1]));
    float gv = tanhf(s[2]),           ov = 1.f/(1.f+expf(-s[3]));
    float cn = fv*__ldcg(&c[e]) + iv*gv;
    c[e] = cn;
    h[e] = ov*tanhf(cn);
}

__device__ __forceinline__ void fc_job(
    int vt, const float* __restrict__ fcW, const float* __restrict__ fcb,
    float* __restrict__ out, float* Ws, float* Xs, int* s_rows,
    float* s_red, int* s_redi)
{
    int tid = threadIdx.x;
    __syncthreads();
    if (tid < 64) s_rows[tid] = tid;
    __syncthreads();
    ull acc[4][2] = {{0,0},{0,0},{0,0},{0,0}};
    gemm_tile(fcW + (size_t)(vt*64)*HID, HID, g_h1, HID, s_rows, 0, HID, Ws, Xs, acc);
    int rg = tid >> 4, cg = tid & 15, v0 = vt*64;
    float4 bv = *(const float4*)&fcb[v0 + cg*4];
    #pragma unroll
    for (int r = 0; r < 4; ++r) {
        int b = rg*4 + r;
        float2 a = unpk(acc[r][0]), d = unpk(acc[r][1]);
        float v_0 = a.x+bv.x, v_1 = a.y+bv.y, v_2 = d.x+bv.z, v_3 = d.y+bv.w;
        *(float4*)&out[(size_t)b*VOCAB + v0 + cg*4] = make_float4(v_0, v_1, v_2, v_3);
        float best = v_0; int bi = 0;
        if (v_1 > best) { best = v_1; bi = 1; }
        if (v_2 > best) { best = v_2; bi = 2; }
        if (v_3 > best) { best = v_3; bi = 3; }
        s_red[b*16 + cg] = best; s_redi[b*16 + cg] = v0 + cg*4 + bi;
    }
    __syncthreads();
    if (tid < 64) {
        float best = s_red[tid*16]; int bi = s_redi[tid*16];
        #pragma unroll
        for (int u = 1; u < 16; ++u) {
            float v = s_red[tid*16 + u];
            if (v > best) { best = v; bi = s_redi[tid*16 + u]; }
        }
        g_pval[vt*BATCH + tid] = best;
        g_pidx[vt*BATCH + tid] = bi;
    }
}

__global__ void __launch_bounds__(NTHR, 2) seq2seq_all(
    const float* __restrict__ enc_embed,
    const float* __restrict__ eWih0, const float* __restrict__ eWhh0,
    const float* __restrict__ ebih0, const float* __restrict__ ebhh0,
    const float* __restrict__ eWih1, const float* __restrict__ eWhh1,
    const float* __restrict__ ebih1, const float* __restrict__ ebhh1,
    const float* __restrict__ dec_embed,
    const float* __restrict__ dWih0, const float* __restrict__ dWhh0,
    const float* __restrict__ dbih0, const float* __restrict__ dbhh0,
    const float* __restrict__ dWih1, const float* __restrict__ dWhh1,
    const float* __restrict__ dbih1, const float* __restrict__ dbhh1,
    const float* __restrict__ fcW, const float* __restrict__ fcb,
    const int* __restrict__ src, const int* __restrict__ target,
    const int* __restrict__ tfmask, float* __restrict__ out)
{
    __shared__ __align__(16) float Ws[2*1088];
    __shared__ __align__(16) float Xs[2*1088];
    __shared__ int   s_rows[64];
    __shared__ float s_red[1024];
    __shared__ int   s_redi[1024];

    int bid = blockIdx.x, tid = threadIdx.x;
    int gtid = bid*NTHR + tid;
    const int GSTR = NBLK*NTHR;

    for (int e = gtid; e < SB; e += GSTR) { g_h0[e]=0.f; g_c0[e]=0.f; g_h1[e]=0.f; g_c1[e]=0.f; }
    for (int e = gtid; e < 2048; e += GSTR) {
        g_bsum[e]      = ebih0[e] + ebhh0[e];
        g_bsum[2048+e] = ebih1[e] + ebhh1[e];
        g_bsum[4096+e] = dbih0[e] + dbhh0[e];
        g_bsum[6144+e] = dbih1[e] + dbhh1[e];
    }
    if (gtid < BATCH) g_xtok[gtid] = target[gtid];
    gridbar();

    // ---- encoder ----
    for (int job = bid; job < 256; job += NBLK)
        gates_job(job, 0, eWih0, eWhh0, enc_embed, src, g_h0, g_parts0, Ws, Xs, s_rows);
    gridbar();
    for (int e = gtid; e < SB; e += GSTR) epi_elem(e, g_bsum, g_parts0, g_h0, g_c0);
    gridbar();
    for (int s = 0; s < SRCLEN-1; ++s) {
        for (int job = bid; job < 512; job += NBLK) {
            if (job < 256)
                gates_job(job, 1, eWih1, eWhh1, g_h0, (const int*)0, g_h1, g_parts1, Ws, Xs, s_rows);
            else
                gates_job(job-256, 0, eWih0, eWhh0, enc_embed, src + (s+1)*BATCH, g_h0, g_parts0, Ws, Xs, s_rows);
        }
        gridbar();
        for (int e = gtid; e < 2*SB; e += GSTR) {
            if (e < SB) epi_elem(e,    g_bsum+2048, g_parts1, g_h1, g_c1);
            else        epi_elem(e-SB, g_bsum,      g_parts0, g_h0, g_c0);
        }
        gridbar();
    }
    for (int job = bid; job < 256; job += NBLK)
        gates_job(job, 1, eWih1, eWhh1, g_h0, (const int*)0, g_h1, g_parts1, Ws, Xs, s_rows);
    gridbar();
    for (int e = gtid; e < SB; e += GSTR) epi_elem(e, g_bsum+2048, g_parts1, g_h1, g_c1);
    gridbar();

    // ---- decoder ----
    for (int t = 1; t < TGTLEN; ++t) {
        for (int job = bid; job < 256; job += NBLK)
            gates_job(job, 0, dWih0, dWhh0, dec_embed, g_xtok, g_h0, g_parts0, Ws, Xs, s_rows);
        gridbar();
        for (int e = gtid; e < SB; e += GSTR) epi_elem(e, g_bsum+4096, g_parts0, g_h0, g_c0);
        gridbar();
        for (int job = bid; job < 256; job += NBLK)
            gates_job(job, 1, dWih1, dWhh1, g_h0, (const int*)0, g_h1, g_parts1, Ws, Xs, s_rows);
        gridbar();
        for (int e = gtid; e < SB; e += GSTR) epi_elem(e, g_bsum+6144, g_parts1, g_h1, g_c1);
        gridbar();

        float* outT = out + (size_t)t*BATCH*VOCAB;
        for (int vt = bid; vt < FCT; vt += NBLK)
            fc_job(vt, fcW, fcb, outT, Ws, Xs, s_rows, s_red, s_redi);
        gridbar();

        if (bid < BATCH) {
            int b = bid;
            int q0 = tid*2;
            float best = -3.4e38f; int bi = 0;
            #pragma unroll
            for (int q = q0; q < q0+2; ++q) {
                if (q < FCT) {
                    float v = __ldcg(&g_pval[q*BATCH + b]);
                    if (v > best) { best = v; bi = __ldcg(&g_pidx[q*BATCH + b]); }
                }
            }
            s_red[tid] = best; s_redi[tid] = bi;
            __syncthreads();
            if (tid == 0) {
                for (int u = 1; u < 256; ++u)
                    if (s_red[u] > best) { best = s_red[u]; bi = s_redi[u]; }
                g_xtok[b] = (tfmask[t] > 0) ? target[t*BATCH + b] : bi;
            }
        }
        gridbar();
    }
}

extern "C" void kernel_launch(void* const* d_in, const int* in_sizes, int n_in,
                              void* d_out, int out_size)
{
    const float *ee,*de,*fw,*fb;
    const float *a1,*a2,*a3,*a4,*a5,*a6,*a7,*a8;
    const float *b1,*b2,*b3,*b4,*b5,*b6,*b7,*b8;
    const int *src,*tgt,*tfm;
    if (in_sizes[0] == SRCLEN*BATCH) {
        src=(const int*)d_in[0]; tgt=(const int*)d_in[1]; tfm=(const int*)d_in[2];
        ee=(const float*)d_in[3]; de=(const float*)d_in[4];
        a1=(const float*)d_in[5];  a2=(const float*)d_in[6];  a3=(const float*)d_in[7];  a4=(const float*)d_in[8];
        a5=(const float*)d_in[9];  a6=(const float*)d_in[10]; a7=(const float*)d_in[11]; a8=(const float*)d_in[12];
        b1=(const float*)d_in[13]; b2=(const float*)d_in[14]; b3=(const float*)d_in[15]; b4=(const float*)d_in[16];
        b5=(const float*)d_in[17]; b6=(const float*)d_in[18]; b7=(const float*)d_in[19]; b8=(const float*)d_in[20];
        fw=(const float*)d_in[21]; fb=(const float*)d_in[22];
    } else {
        ee=(const float*)d_in[0];
        a1=(const float*)d_in[1];  a2=(const float*)d_in[2];  a3=(const float*)d_in[3];  a4=(const float*)d_in[4];
        a5=(const float*)d_in[5];  a6=(const float*)d_in[6];  a7=(const float*)d_in[7];  a8=(const float*)d_in[8];
        de=(const float*)d_in[9];
        b1=(const float*)d_in[10]; b2=(const float*)d_in[11]; b3=(const float*)d_in[12]; b4=(const float*)d_in[13];
        b5=(const float*)d_in[14]; b6=(const float*)d_in[15]; b7=(const float*)d_in[16]; b8=(const float*)d_in[17];
        fw=(const float*)d_in[18]; fb=(const float*)d_in[19];
        src=(const int*)d_in[20]; tgt=(const int*)d_in[21]; tfm=(const int*)d_in[22];
    }
    float* out = (float*)d_out;
    cudaMemsetAsync(out, 0, (size_t)BATCH*VOCAB*sizeof(float));
    seq2seq_all<<<NBLK, NTHR>>>(ee, a1,a2,a3,a4, a5,a6,a7,a8,
                                de, b1,b2,b3,b4, b5,b6,b7,b8,
                                fw, fb, src, tgt, tfm, out);
}